// round 3
// baseline (speedup 1.0000x reference)
#include <cuda_runtime.h>
#include <cuda_fp16.h>
#include <cstdint>

// ---------------- problem constants ----------------
#define N_ROWS 16384
#define DF     128
#define KC     32                 // K chunk per pipeline stage
#define NITER  (N_ROWS / KC)      // 512
#define NSTG   4                  // cp.async ring depth

// XW = x @ W, packed as half2 pairs along j (row j/2 holds {XW[2k][d], XW[2k+1][d]}).
__device__ uint32_t g_XWp[(size_t)(N_ROWS / 2) * DF];   // 4 MiB

__device__ __forceinline__ uint32_t packh2(float lo, float hi) {
    __half2 h = __floats2half2_rn(lo, hi);
    return *(uint32_t*)&h;
}
__device__ __forceinline__ uint32_t smem_u32(const void* p) {
    uint32_t a;
    asm("{ .reg .u64 t; cvta.to.shared.u64 t, %1; cvt.u32.u64 %0, t; }" : "=r"(a) : "l"(p));
    return a;
}
__device__ __forceinline__ void cp_async16(uint32_t dst, const void* src) {
    asm volatile("cp.async.cg.shared.global [%0], [%1], 16;" :: "r"(dst), "l"(src));
}
#define CP_COMMIT() asm volatile("cp.async.commit_group;" ::: "memory")
#define CP_WAIT(n)  asm volatile("cp.async.wait_group %0;" :: "n"(n) : "memory")

// ---------------- kernel 1: XW = x @ W (fp32 compute, fp16-pair store) ----------------
#define XW_SMEM ((128 * 132 + 128 * 128) * 4)

__global__ void __launch_bounds__(256) xw_kernel(const float* __restrict__ x,
                                                 const float* __restrict__ W) {
    extern __shared__ float sm_xw[];
    float* xsT = sm_xw;              // [128][132] transposed x tile (padded)
    float* Ws  = sm_xw + 128 * 132;  // [128][128]
    const int tid = threadIdx.x;
    const int j0 = blockIdx.x * 128;

    for (int idx = tid; idx < 128 * 128; idx += 256) {
        int j = idx >> 7, k = idx & 127;
        xsT[k * 132 + j] = x[(size_t)(j0 + j) * DF + k];
        Ws[idx] = W[idx];
    }
    __syncthreads();

    const int tx = tid & 15, ty = tid >> 4;
    const int jb = ty * 8, db = tx * 8;
    float acc[8][8];
#pragma unroll
    for (int a = 0; a < 8; a++)
#pragma unroll
        for (int b = 0; b < 8; b++) acc[a][b] = 0.0f;

    for (int k = 0; k < 128; k++) {
        float4 a0 = *(const float4*)(xsT + k * 132 + jb);
        float4 a1 = *(const float4*)(xsT + k * 132 + jb + 4);
        float4 b0 = *(const float4*)(Ws + k * 128 + db);
        float4 b1 = *(const float4*)(Ws + k * 128 + db + 4);
        float aa[8] = {a0.x, a0.y, a0.z, a0.w, a1.x, a1.y, a1.z, a1.w};
        float bb[8] = {b0.x, b0.y, b0.z, b0.w, b1.x, b1.y, b1.z, b1.w};
#pragma unroll
        for (int jj = 0; jj < 8; jj++)
#pragma unroll
            for (int dd = 0; dd < 8; dd++) acc[jj][dd] += aa[jj] * bb[dd];
    }

    const uint32_t jp = (uint32_t)((j0 + jb) >> 1);
#pragma unroll
    for (int q = 0; q < 4; q++) {
        uint32_t* dst = g_XWp + (size_t)(jp + q) * DF + db;
        uint4 v0, v1;
        v0.x = packh2(acc[2 * q][0], acc[2 * q + 1][0]);
        v0.y = packh2(acc[2 * q][1], acc[2 * q + 1][1]);
        v0.z = packh2(acc[2 * q][2], acc[2 * q + 1][2]);
        v0.w = packh2(acc[2 * q][3], acc[2 * q + 1][3]);
        v1.x = packh2(acc[2 * q][4], acc[2 * q + 1][4]);
        v1.y = packh2(acc[2 * q][5], acc[2 * q + 1][5]);
        v1.z = packh2(acc[2 * q][6], acc[2 * q + 1][6]);
        v1.w = packh2(acc[2 * q][7], acc[2 * q + 1][7]);
        *(uint4*)dst = v0;
        *(uint4*)(dst + 4) = v1;
    }
}

// ---------------- kernel 2: fused exp + softmax-GEMM, cp.async pipelined ----------------
// SMEM layout (bytes):
//   ADJ ring: 4 stages x [128 rows x 144B (32 f32 + 16B pad)] = 73728
//   B   ring: 4 stages x [16 pair-rows x 544B (136 u32)]      = 34816
//   A   ring: 2 slots  x [128 rows x 80B (20 u32)]            = 20480
//   rowsums 512B, bias 512B
#define ADJ_STRIDE_B 144
#define ADJ_STG_B    (128 * ADJ_STRIDE_B)        // 18432
#define SA2 20
#define SB2 136
#define B_STG_B      (16 * SB2 * 4)              // 8704
#define A_SLOT_B     (128 * SA2 * 4)             // 10240
#define ADJ_OFF  0u
#define B_OFF    (ADJ_OFF + NSTG * ADJ_STG_B)    // 73728
#define A_OFF    (B_OFF + NSTG * B_STG_B)        // 108544
#define RS_OFF   (A_OFF + 2 * A_SLOT_B)          // 129024
#define BIAS_OFF (RS_OFF + 512)                  // 129536
#define FUSED_SMEM (BIAS_OFF + 512)              // 130048

__global__ void __launch_bounds__(256) fused_kernel(const float* __restrict__ adj,
                                                    const float* __restrict__ bias,
                                                    float* __restrict__ out) {
    extern __shared__ char sm8[];
    const uint32_t sb = smem_u32(sm8);
    float* rs = (float*)(sm8 + RS_OFF);
    float* bs = (float*)(sm8 + BIAS_OFF);

    const int tid = threadIdx.x;
    const int wid = tid >> 5;
    const int lid = tid & 31;
    const int m0 = blockIdx.x * 128;

    if (tid < DF) bs[tid] = bias[tid];

    // ---- producer mappings ----
    const int r = tid >> 1;            // adj row within tile (0..127)
    const int hf = tid & 1;            // 16-float half of the 32-col chunk
    const float* agsrc = adj + (size_t)(m0 + r) * N_ROWS + hf * 16;
    const uint32_t adj_dst = sb + ADJ_OFF + (uint32_t)r * ADJ_STRIDE_B + hf * 64;
    const uint32_t a_sts = (uint32_t)r * SA2 + hf * 8;   // u32 units in A slot

    const int kk = tid >> 4;           // pair-row within B chunk (0..15)
    const int nb = tid & 15;           // 8-u32 col block
    const uint32_t* bgsrc = g_XWp + (size_t)kk * DF + nb * 8;
    const uint32_t b_dst = sb + B_OFF + ((uint32_t)kk * SB2 + nb * 8) * 4;

    // ---- consumer mapping ----
    const int g = lid >> 2, tg = lid & 3;
    const int mB = (wid & 3) * 32;
    const int nB = (wid >> 2) * 64;

    float rsum = 0.0f;
    float acc[2][8][4];
#pragma unroll
    for (int i = 0; i < 2; i++)
#pragma unroll
        for (int j = 0; j < 8; j++)
#pragma unroll
            for (int c = 0; c < 4; c++) acc[i][j][c] = 0.0f;

    // issue cp.asyncs for chunk `cn` into ring stage cn&3, one commit group
#define ISSUE(cn) do {                                                             \
        const uint32_t stg = (uint32_t)((cn) & 3);                                 \
        const float* asp = agsrc + (size_t)(cn) * KC;                              \
        uint32_t ad = adj_dst + stg * ADJ_STG_B;                                   \
        cp_async16(ad,      asp);                                                  \
        cp_async16(ad + 16, asp + 4);                                              \
        cp_async16(ad + 32, asp + 8);                                              \
        cp_async16(ad + 48, asp + 12);                                             \
        const uint32_t* bsp = bgsrc + (size_t)(cn) * 16 * DF;                      \
        uint32_t bd = b_dst + stg * B_STG_B;                                       \
        cp_async16(bd,      bsp);                                                  \
        cp_async16(bd + 16, bsp + 4);                                              \
        CP_COMMIT();                                                               \
    } while (0)

    // prologue: stages 0..2
    ISSUE(0);
    ISSUE(1);
    ISSUE(2);

    for (int it = 0; it < NITER; ++it) {
        const int stg = it & 3;
        const int slot = it & 1;

        if (it < NITER - 2) { CP_WAIT(2); } else { CP_WAIT(0); }
        __syncthreads();               // stage `it` visible; prev MMA done (safe to overwrite)

        if (it + 3 < NITER) ISSUE(it + 3);

        // convert: exp(adj stage) -> fp16 A slot; accumulate rowsum
        {
            const float4* ap = (const float4*)(sm8 + ADJ_OFF + (size_t)stg * ADJ_STG_B
                                               + (size_t)r * ADJ_STRIDE_B + hf * 64);
            uint32_t pk[8];
#pragma unroll
            for (int q = 0; q < 4; q++) {
                float4 v = ap[q];
                float e0 = __expf(v.x), e1 = __expf(v.y);
                float e2 = __expf(v.z), e3 = __expf(v.w);
                rsum += (e0 + e1) + (e2 + e3);
                pk[2 * q]     = packh2(e0, e1);
                pk[2 * q + 1] = packh2(e2, e3);
            }
            uint32_t* As = (uint32_t*)(sm8 + A_OFF + (size_t)slot * A_SLOT_B);
            *(uint4*)(As + a_sts)     = make_uint4(pk[0], pk[1], pk[2], pk[3]);
            *(uint4*)(As + a_sts + 4) = make_uint4(pk[4], pk[5], pk[6], pk[7]);
        }
        __syncthreads();               // A slot ready

        // MMA on A slot + B stage
        const uint32_t* As = (const uint32_t*)(sm8 + A_OFF + (size_t)slot * A_SLOT_B);
        const uint32_t* Bs = (const uint32_t*)(sm8 + B_OFF + (size_t)stg * B_STG_B);
#pragma unroll
        for (int ks = 0; ks < 2; ks++) {
            uint32_t af[2][4];
#pragma unroll
            for (int mi = 0; mi < 2; mi++) {
                const uint32_t* Ar = As + (mB + mi * 16 + g) * SA2 + ks * 8 + tg;
                af[mi][0] = Ar[0];
                af[mi][1] = Ar[8 * SA2];
                af[mi][2] = Ar[4];
                af[mi][3] = Ar[8 * SA2 + 4];
            }
#pragma unroll
            for (int ni = 0; ni < 8; ni++) {
                const uint32_t* Br = Bs + (ks * 8 + tg) * SB2 + nB + ni * 8 + g;
                uint32_t b0 = Br[0];
                uint32_t b1 = Br[4 * SB2];
#pragma unroll
                for (int mi = 0; mi < 2; mi++) {
                    asm volatile(
                        "mma.sync.aligned.m16n8k16.row.col.f32.f16.f16.f32 "
                        "{%0,%1,%2,%3}, {%4,%5,%6,%7}, {%8,%9}, {%0,%1,%2,%3};"
                        : "+f"(acc[mi][ni][0]), "+f"(acc[mi][ni][1]),
                          "+f"(acc[mi][ni][2]), "+f"(acc[mi][ni][3])
                        : "r"(af[mi][0]), "r"(af[mi][1]), "r"(af[mi][2]), "r"(af[mi][3]),
                          "r"(b0), "r"(b1));
                }
            }
        }
    }

    // ---- rowsums ----
    rsum += __shfl_xor_sync(0xffffffffu, rsum, 1);
    if (hf == 0) rs[r] = rsum;
    __syncthreads();

    // ---- epilogue: divide + bias + store ----
#pragma unroll
    for (int mi = 0; mi < 2; mi++) {
        const int r0 = mB + mi * 16 + g;
        const int r1 = r0 + 8;
        const float inv0 = 1.0f / rs[r0];
        const float inv1 = 1.0f / rs[r1];
#pragma unroll
        for (int ni = 0; ni < 8; ni++) {
            const int c = nB + ni * 8 + 2 * tg;
            const float b0v = bs[c];
            const float b1v = bs[c + 1];
            float2 o;
            o.x = acc[mi][ni][0] * inv0 + b0v;
            o.y = acc[mi][ni][1] * inv0 + b1v;
            *(float2*)(out + (size_t)(m0 + r0) * DF + c) = o;
            o.x = acc[mi][ni][2] * inv1 + b0v;
            o.y = acc[mi][ni][3] * inv1 + b1v;
            *(float2*)(out + (size_t)(m0 + r1) * DF + c) = o;
        }
    }
}

// ---------------- launcher ----------------
extern "C" void kernel_launch(void* const* d_in, const int* in_sizes, int n_in,
                              void* d_out, int out_size) {
    const float* x   = (const float*)d_in[0];
    const float* adj = (const float*)d_in[1];
    const float* W   = (const float*)d_in[2];
    const float* b   = (const float*)d_in[3];
    float* out = (float*)d_out;
    (void)in_sizes; (void)n_in; (void)out_size;

    cudaFuncSetAttribute(xw_kernel, cudaFuncAttributeMaxDynamicSharedMemorySize, XW_SMEM);
    cudaFuncSetAttribute(fused_kernel, cudaFuncAttributeMaxDynamicSharedMemorySize, FUSED_SMEM);

    xw_kernel<<<N_ROWS / 128, 256, XW_SMEM>>>(x, W);
    fused_kernel<<<N_ROWS / 128, 256, FUSED_SMEM>>>(adj, b, out);
}

// round 4
// speedup vs baseline: 1.4078x; 1.4078x over previous
#include <cuda_runtime.h>
#include <cuda_fp16.h>
#include <cstdint>

// ---------------- problem constants ----------------
#define N_ROWS 16384
#define DF     128
#define KC     32                 // K chunk per ring stage
#define NITER  (N_ROWS / KC)      // 512
#define NSTG   4                  // ring depth

// XW = x @ W, packed as half2 pairs along j (row j/2 holds {XW[2k][d], XW[2k+1][d]}).
__device__ uint32_t g_XWp[(size_t)(N_ROWS / 2) * DF];   // 4 MiB

__device__ __forceinline__ uint32_t packh2(float lo, float hi) {
    __half2 h = __floats2half2_rn(lo, hi);
    return *(uint32_t*)&h;
}
__device__ __forceinline__ uint32_t smem_u32(const void* p) {
    uint32_t a;
    asm("{ .reg .u64 t; cvta.to.shared.u64 t, %1; cvt.u32.u64 %0, t; }" : "=r"(a) : "l"(p));
    return a;
}
__device__ __forceinline__ void cp_async16(uint32_t dst, const void* src) {
    asm volatile("cp.async.cg.shared.global [%0], [%1], 16;" :: "r"(dst), "l"(src));
}
#define CP_COMMIT() asm volatile("cp.async.commit_group;" ::: "memory")
#define CP_WAIT(n)  asm volatile("cp.async.wait_group %0;" :: "n"(n) : "memory")

__device__ __forceinline__ void bar_sync_named(int id) {
    asm volatile("bar.sync %0, 512;" :: "r"(id) : "memory");
}
__device__ __forceinline__ void bar_arrive_named(int id) {
    asm volatile("bar.arrive %0, 512;" :: "r"(id) : "memory");
}
#define BAR_FULL(s)  ((s) + 1)
#define BAR_EMPTY(s) ((s) + 5)

// ---------------- kernel 1: XW = x @ W (fp32 compute, fp16-pair store) ----------------
#define XW_SMEM ((128 * 132 + 128 * 128) * 4)

__global__ void __launch_bounds__(256) xw_kernel(const float* __restrict__ x,
                                                 const float* __restrict__ W) {
    extern __shared__ float sm_xw[];
    float* xsT = sm_xw;              // [128][132] transposed x tile
    float* Ws  = sm_xw + 128 * 132;  // [128][128]
    const int tid = threadIdx.x;
    const int j0 = blockIdx.x * 128;

    for (int idx = tid; idx < 128 * 128; idx += 256) {
        int j = idx >> 7, k = idx & 127;
        xsT[k * 132 + j] = x[(size_t)(j0 + j) * DF + k];
        Ws[idx] = W[idx];
    }
    __syncthreads();

    const int tx = tid & 15, ty = tid >> 4;
    const int jb = ty * 8, db = tx * 8;
    float acc[8][8];
#pragma unroll
    for (int a = 0; a < 8; a++)
#pragma unroll
        for (int b = 0; b < 8; b++) acc[a][b] = 0.0f;

    for (int k = 0; k < 128; k++) {
        float4 a0 = *(const float4*)(xsT + k * 132 + jb);
        float4 a1 = *(const float4*)(xsT + k * 132 + jb + 4);
        float4 b0 = *(const float4*)(Ws + k * 128 + db);
        float4 b1 = *(const float4*)(Ws + k * 128 + db + 4);
        float aa[8] = {a0.x, a0.y, a0.z, a0.w, a1.x, a1.y, a1.z, a1.w};
        float bb[8] = {b0.x, b0.y, b0.z, b0.w, b1.x, b1.y, b1.z, b1.w};
#pragma unroll
        for (int jj = 0; jj < 8; jj++)
#pragma unroll
            for (int dd = 0; dd < 8; dd++) acc[jj][dd] += aa[jj] * bb[dd];
    }

    const uint32_t jp = (uint32_t)((j0 + jb) >> 1);
#pragma unroll
    for (int q = 0; q < 4; q++) {
        uint32_t* dst = g_XWp + (size_t)(jp + q) * DF + db;
        uint4 v0, v1;
        v0.x = packh2(acc[2 * q][0], acc[2 * q + 1][0]);
        v0.y = packh2(acc[2 * q][1], acc[2 * q + 1][1]);
        v0.z = packh2(acc[2 * q][2], acc[2 * q + 1][2]);
        v0.w = packh2(acc[2 * q][3], acc[2 * q + 1][3]);
        v1.x = packh2(acc[2 * q][4], acc[2 * q + 1][4]);
        v1.y = packh2(acc[2 * q][5], acc[2 * q + 1][5]);
        v1.z = packh2(acc[2 * q][6], acc[2 * q + 1][6]);
        v1.w = packh2(acc[2 * q][7], acc[2 * q + 1][7]);
        *(uint4*)dst = v0;
        *(uint4*)(dst + 4) = v1;
    }
}

// ---------------- kernel 2: warp-specialized fused exp + softmax-GEMM ----------------
// 512 threads: tid<256 = MMA consumers (8 warps), tid>=256 = producers (8 warps).
// Ring: 4 stages x { A: 128x20 u32 fp16-pairs (10240B), B: 16x136 u32 (8704B) }.
#define SA2 20
#define SB2 136
#define A_STG_B  (128 * SA2 * 4)                 // 10240
#define B_STG_B  (16 * SB2 * 4)                  // 8704
#define A_OFF    0u
#define B_OFF    (A_OFF + NSTG * A_STG_B)        // 40960
#define RS_OFF   (B_OFF + NSTG * B_STG_B)        // 75776
#define BIAS_OFF (RS_OFF + 512)                  // 76288
#define FUSED_SMEM (BIAS_OFF + 512)              // 76800

__global__ void __launch_bounds__(512, 1) fused_kernel(const float* __restrict__ adj,
                                                       const float* __restrict__ bias,
                                                       float* __restrict__ out) {
    extern __shared__ char sm8[];
    const uint32_t sb = smem_u32(sm8);
    float* rs = (float*)(sm8 + RS_OFF);
    float* bs = (float*)(sm8 + BIAS_OFF);

    const int tid = threadIdx.x;
    const int m0 = blockIdx.x * 128;

    if (tid < DF) bs[tid] = bias[tid];   // consumers idle-load bias (visible by final syncthreads)

    if (tid >= 256) {
        // ================= PRODUCERS =================
        const int ptid = tid - 256;
        const int r = ptid >> 1;           // adj row within tile
        const int hf = ptid & 1;           // 16-float half of 32-col chunk
        const float* agsrc = adj + (size_t)(m0 + r) * N_ROWS + hf * 16;
        const uint32_t a_sts = (uint32_t)r * SA2 + hf * 8;   // u32 units

        const int kk = ptid >> 4;          // pair-row (0..15)
        const int nb = ptid & 15;          // 8-u32 col block
        const uint32_t* bgsrc = g_XWp + (size_t)kk * DF + nb * 8;
        const uint32_t b_dst = sb + B_OFF + ((uint32_t)kk * SB2 + nb * 8) * 4;

        float4 a0b[4], a1b[4];
        float rsum = 0.0f;

#define LDGA(cn, BUF) do {                                                       \
            const float* _p = agsrc + (size_t)(cn) * KC;                         \
            BUF[0] = *(const float4*)(_p);                                       \
            BUF[1] = *(const float4*)(_p + 4);                                   \
            BUF[2] = *(const float4*)(_p + 8);                                   \
            BUF[3] = *(const float4*)(_p + 12);                                  \
        } while (0)
#define CPB(cn) do {                                                             \
            const uint32_t* _p = bgsrc + (size_t)(cn) * 16 * DF;                 \
            uint32_t _d = b_dst + (uint32_t)((cn) & 3) * B_STG_B;                \
            cp_async16(_d, _p);                                                  \
            cp_async16(_d + 16, _p + 4);                                         \
        } while (0)

        // prologue: chunks 0,1 (A regs + B groups); stages fresh, no empty-wait
        LDGA(0, a0b);
        LDGA(1, a1b);
        CPB(0); CP_COMMIT();
        CPB(1); CP_COMMIT();

#define PBODY(cn, BUF) do {                                                      \
            const int _s = (cn) & 3;                                             \
            /* exp + pack + STS A(cn); stage empty since iter cn-2 */            \
            uint32_t pk[8];                                                      \
            _Pragma("unroll")                                                    \
            for (int q = 0; q < 4; q++) {                                        \
                float e0 = __expf(BUF[q].x), e1 = __expf(BUF[q].y);              \
                float e2 = __expf(BUF[q].z), e3 = __expf(BUF[q].w);              \
                rsum += (e0 + e1) + (e2 + e3);                                   \
                pk[2 * q]     = packh2(e0, e1);                                  \
                pk[2 * q + 1] = packh2(e2, e3);                                  \
            }                                                                    \
            uint32_t* As = (uint32_t*)(sm8 + A_OFF + (size_t)_s * A_STG_B);      \
            *(uint4*)(As + a_sts)     = make_uint4(pk[0], pk[1], pk[2], pk[3]);  \
            *(uint4*)(As + a_sts + 4) = make_uint4(pk[4], pk[5], pk[6], pk[7]);  \
            /* prefetch chunk cn+2 into the buffer just freed */                 \
            if ((cn) + 2 < NITER) {                                              \
                if ((cn) + 2 >= NSTG) bar_sync_named(BAR_EMPTY(((cn) + 2) & 3)); \
                CPB((cn) + 2);                                                   \
                LDGA((cn) + 2, BUF);                                             \
            }                                                                    \
            CP_COMMIT();                                                         \
            CP_WAIT(2);      /* B(cn) complete (2 newer groups outstanding) */   \
            __threadfence_block();                                               \
            bar_arrive_named(BAR_FULL(_s));                                      \
        } while (0)

        for (int cn = 0; cn < NITER; cn += 2) {
            PBODY(cn, a0b);
            PBODY(cn + 1, a1b);
        }

        // rowsums: combine the two producer threads sharing a row
        rsum += __shfl_xor_sync(0xffffffffu, rsum, 1);
        if (hf == 0) rs[r] = rsum;
        __syncthreads();
        // producers done (consumers do epilogue)
    } else {
        // ================= CONSUMERS =================
        const int wid = tid >> 5;
        const int lid = tid & 31;
        const int g = lid >> 2, tg = lid & 3;
        const int mB = (wid & 3) * 32;
        const int nB = (wid >> 2) * 64;

        float acc[2][8][4];
#pragma unroll
        for (int i = 0; i < 2; i++)
#pragma unroll
            for (int j = 0; j < 8; j++)
#pragma unroll
                for (int c = 0; c < 4; c++) acc[i][j][c] = 0.0f;

        for (int it = 0; it < NITER; ++it) {
            const int s = it & 3;
            bar_sync_named(BAR_FULL(s));

            const uint32_t* As = (const uint32_t*)(sm8 + A_OFF + (size_t)s * A_STG_B);
            const uint32_t* Bs = (const uint32_t*)(sm8 + B_OFF + (size_t)s * B_STG_B);
#pragma unroll
            for (int ks = 0; ks < 2; ks++) {
                uint32_t af[2][4];
#pragma unroll
                for (int mi = 0; mi < 2; mi++) {
                    const uint32_t* Ar = As + (mB + mi * 16 + g) * SA2 + ks * 8 + tg;
                    af[mi][0] = Ar[0];
                    af[mi][1] = Ar[8 * SA2];
                    af[mi][2] = Ar[4];
                    af[mi][3] = Ar[8 * SA2 + 4];
                }
#pragma unroll
                for (int ni = 0; ni < 8; ni++) {
                    const uint32_t* Br = Bs + (ks * 8 + tg) * SB2 + nB + ni * 8 + g;
                    uint32_t b0 = Br[0];
                    uint32_t b1 = Br[4 * SB2];
#pragma unroll
                    for (int mi = 0; mi < 2; mi++) {
                        asm volatile(
                            "mma.sync.aligned.m16n8k16.row.col.f32.f16.f16.f32 "
                            "{%0,%1,%2,%3}, {%4,%5,%6,%7}, {%8,%9}, {%0,%1,%2,%3};"
                            : "+f"(acc[mi][ni][0]), "+f"(acc[mi][ni][1]),
                              "+f"(acc[mi][ni][2]), "+f"(acc[mi][ni][3])
                            : "r"(af[mi][0]), "r"(af[mi][1]), "r"(af[mi][2]), "r"(af[mi][3]),
                              "r"(b0), "r"(b1));
                    }
                }
            }
            // HMMAs consumed the LDS results -> safe to release the stage
            bar_arrive_named(BAR_EMPTY(s));
        }

        __syncthreads();   // rowsums + bias visible

        // epilogue: divide + bias + store
#pragma unroll
        for (int mi = 0; mi < 2; mi++) {
            const int r0 = mB + mi * 16 + g;
            const int r1 = r0 + 8;
            const float inv0 = 1.0f / rs[r0];
            const float inv1 = 1.0f / rs[r1];
#pragma unroll
            for (int ni = 0; ni < 8; ni++) {
                const int c = nB + ni * 8 + 2 * tg;
                const float b0v = bs[c];
                const float b1v = bs[c + 1];
                float2 o;
                o.x = acc[mi][ni][0] * inv0 + b0v;
                o.y = acc[mi][ni][1] * inv0 + b1v;
                *(float2*)(out + (size_t)(m0 + r0) * DF + c) = o;
                o.x = acc[mi][ni][2] * inv1 + b0v;
                o.y = acc[mi][ni][3] * inv1 + b1v;
                *(float2*)(out + (size_t)(m0 + r1) * DF + c) = o;
            }
        }
    }
}

// ---------------- launcher ----------------
extern "C" void kernel_launch(void* const* d_in, const int* in_sizes, int n_in,
                              void* d_out, int out_size) {
    const float* x   = (const float*)d_in[0];
    const float* adj = (const float*)d_in[1];
    const float* W   = (const float*)d_in[2];
    const float* b   = (const float*)d_in[3];
    float* out = (float*)d_out;
    (void)in_sizes; (void)n_in; (void)out_size;

    cudaFuncSetAttribute(xw_kernel, cudaFuncAttributeMaxDynamicSharedMemorySize, XW_SMEM);
    cudaFuncSetAttribute(fused_kernel, cudaFuncAttributeMaxDynamicSharedMemorySize, FUSED_SMEM);

    xw_kernel<<<N_ROWS / 128, 256, XW_SMEM>>>(x, W);
    fused_kernel<<<N_ROWS / 128, 512, FUSED_SMEM>>>(adj, b, out);
}